// round 16
// baseline (speedup 1.0000x reference)
#include <cuda_runtime.h>

// ---------------------------------------------------------------------------
// SinkhornDistance (degenerate loop):
//   out[b] = sum_{i,j} g(xs_i-ys_j, x_i-y_j), g(d1,d2)=c*exp(-10c), c=d1^2+d2^2
// Chebyshev tensor algebra, POLYNOMIAL moments (R15 phase 1):
//   M[j,k] = sum_i T_j(u_i) T_k(v_i)   (3-term recurrence, no MUFU)
// R16: overlap the node-constant transform. 8 dedicated finisher blocks
// compute St = a^T S a, Kt = a^T K a DURING phase 1, spin on the per-batch
// counter, then a 3-pass tail using symmetry:
//   out[b] = <St*Mx, My*Kt> + <Kt*Mx, My*St>.
// Graph-replay safe: finisher re-zeroes g_W and resets its counter.
// ---------------------------------------------------------------------------

#define NCH    32
#define NPTS   4096
#define NB     8
#define CHUNK  128
#define NCHUNK (NPTS / CHUNK)          // 32
#define BLK_PER_BATCH (2 * NCHUNK)     // 64
#define GRID_MOM (NB * BLK_PER_BATCH)  // 512
#define GRID   (GRID_MOM + NB)         // 520 (8 finishers)
#define TPB    256
#define PI     33                      // 32-bit pitch, conflict-free
#define API    17                      // A pitch in 64-bit pairs: 2-way stores

#define PACK2(out, lo, hi)  asm("mov.b64 %0, {%1, %2};" : "=l"(out) : "f"(lo), "f"(hi))
#define UNPACK2(lo, hi, in) asm("mov.b64 {%0, %1}, %2;" : "=f"(lo), "=f"(hi) : "l"(in))
#define ADD2(out, a, b)     asm("add.rn.f32x2 %0, %1, %2;" : "=l"(out) : "l"(a), "l"(b))
#define FMA2(out, a, b, c)  asm("fma.rn.f32x2 %0, %1, %2, %3;" : "=l"(out) : "l"(a), "l"(b), "l"(c))

__device__ float g_W[NB * 2 * NCH * NCH];   // Chebyshev moments; re-zeroed
__device__ unsigned int g_cnt[NB];          // per-batch arrivals; reset by owner

struct MomSh {
    unsigned long long A64[CHUNK * API];    // [pt][T-pair]   (17408 B)
    float B[CHUNK * PI];                    // [pt][T_j]      (16896 B)
};
struct FinSh {                              // 9 x 4224 B = 38016 B
    float Mx[NCH * PI], My[NCH * PI];
    float St[NCH * PI], Kt[NCH * PI];
    float P1[NCH * PI], P2[NCH * PI];       // also: S, K during phase A
    float Al[NCH * PI];
    float T1[NCH * PI], T2[NCH * PI];
    float red[TPB / 32];
};

// dst = A * B (32x32, pitch PI); 4 elements per thread; r uniform per warp.
__device__ __forceinline__ void mm32(float* dst, const float* A, const float* B,
                                     int tid) {
#pragma unroll
    for (int k = 0; k < 4; k++) {
        const int o = tid + TPB * k;
        const int r = o >> 5, c = o & 31;
        float acc = 0.0f;
#pragma unroll
        for (int i = 0; i < NCH; i++)
            acc = fmaf(A[r * PI + i], B[i * PI + c], acc);  // bcast + coalesced
        dst[r * PI + c] = acc;
    }
}

// dst = A^T * B
__device__ __forceinline__ void mmT32(float* dst, const float* A, const float* B,
                                      int tid) {
#pragma unroll
    for (int k = 0; k < 4; k++) {
        const int o = tid + TPB * k;
        const int r = o >> 5, c = o & 31;
        float acc = 0.0f;
#pragma unroll
        for (int i = 0; i < NCH; i++)
            acc = fmaf(A[i * PI + r], B[i * PI + c], acc);
        dst[r * PI + c] = acc;
    }
}

__global__ void __launch_bounds__(TPB, 4) k_fused(
    const float* __restrict__ x,  const float* __restrict__ y,
    const float* __restrict__ xs, const float* __restrict__ ys,
    float* __restrict__ out)
{
    __shared__ __align__(16) union { MomSh m; FinSh f; } sm;

    const int tid = threadIdx.x;
    const int blk = blockIdx.x;

    if (blk < GRID_MOM) {
        // ================= MOMENT BLOCK (R15 phase 1) =================
        const int chunk = blk & (NCHUNK - 1);
        const int side  = (blk >> 5) & 1;
        const int batch = blk >> 6;
        const float* A  = side ? ys : xs;
        const float* Bv = side ? y  : x;
        const int base  = batch * NPTS + chunk * CHUNK;

        // Chebyshev values via recurrence (1 task per thread)
        {
            const int pt    = tid & (CHUNK - 1);
            const int which = tid >> 7;
            float v  = which ? Bv[base + pt] : A[base + pt];
            float xi = 2.0f * v - 1.0f;
            float x2 = xi + xi;
            float t0 = 1.0f, t1 = xi;
            if (which) {
                float* brow = sm.m.B + pt * PI;
                brow[0] = t0;
                brow[1] = t1;
#pragma unroll
                for (int j = 2; j < NCH; j += 2) {
                    t0 = fmaf(x2, t1, -t0);
                    brow[j] = t0;
                    t1 = fmaf(x2, t0, -t1);
                    brow[j + 1] = t1;
                }
            } else {
                unsigned long long* arow = sm.m.A64 + pt * API;
                unsigned long long pr;
                PACK2(pr, t0, t1);
                arow[0] = pr;
#pragma unroll
                for (int m = 1; m < 16; m++) {
                    t0 = fmaf(x2, t1, -t0);
                    t1 = fmaf(x2, t0, -t1);
                    PACK2(pr, t0, t1);
                    arow[m] = pr;
                }
            }
        }
        __syncthreads();

        // Outer-product GEMM, 2-way a-split
        {
            const int w    = tid >> 5;
            const int lane = tid & 31;
            const int ah   = (w & 1) * 8;
            const int p0   = (w >> 1) * 32;

            unsigned long long acc[8];
#pragma unroll
            for (int a2 = 0; a2 < 8; a2++) acc[a2] = 0ull;

            const unsigned long long* abase = sm.m.A64 + p0 * API + ah;
            const float*              bbase = sm.m.B   + p0 * PI + lane;

#pragma unroll 4
            for (int i = 0; i < 32; i++) {
                float bv = bbase[i * PI];
                unsigned long long bv2;
                PACK2(bv2, bv, bv);
#pragma unroll
                for (int a2 = 0; a2 < 8; a2++)
                    FMA2(acc[a2], abase[i * API + a2], bv2, acc[a2]);
            }

            __syncthreads();
            unsigned long long* red64 = reinterpret_cast<unsigned long long*>(&sm);
#pragma unroll
            for (int a2 = 0; a2 < 8; a2++)
                red64[w * 256 + a2 * 32 + lane] = acc[a2];
            __syncthreads();

            float* Wp = g_W + (batch * 2 + side) * NCH * NCH;
#pragma unroll
            for (int k = 0; k < 2; k++) {
                const int o     = tid + TPB * k;
                const int h     = o >> 8;
                const int local = o & 255;
                unsigned long long v2, v3;
                ADD2(v2, red64[h * 256 + local],       red64[(h + 2) * 256 + local]);
                ADD2(v3, red64[(h + 4) * 256 + local], red64[(h + 6) * 256 + local]);
                ADD2(v2, v2, v3);
                float lo, hi;
                UNPACK2(lo, hi, v2);
                const int fo = ((o >> 5) << 6) + (o & 31);
                atomicAdd(&Wp[fo],      lo);
                atomicAdd(&Wp[fo + 32], hi);
            }
        }

        __threadfence();
        __syncthreads();
        if (tid == 0) atomicAdd(&g_cnt[batch], 1u);
        return;
    }

    // ================= FINISHER BLOCK (one per batch) =================
    const int b = blk - GRID_MOM;

    // ---- phase A (overlapped with phase 1): node-constant transform ----
    // S,K in P1,P2; Al = alpha;  St = Al^T S Al, Kt = Al^T K Al.
#pragma unroll
    for (int k = 0; k < 4; k++) {
        const int o = tid + TPB * k;
        const int r = o >> 5, c = o & 31;
        float beta = (c == 0) ? (1.0f / 32.0f) : (1.0f / 16.0f);
        sm.f.Al[r * PI + c] =
            beta * cospif((float)(c * (2 * r + 1)) * (1.0f / 64.0f));
        float pa = cospif((2.0f * r + 1.0f) / 64.0f);
        float pc = cospif((2.0f * c + 1.0f) / 64.0f);
        float dd = 0.5f * (pa - pc);
        float c2 = dd * dd;
        float e  = expf(-10.0f * c2);
        sm.f.P1[r * PI + c] = c2 * e;       // S
        sm.f.P2[r * PI + c] = e;            // K
    }
    __syncthreads();

    mm32 (sm.f.T1, sm.f.P1, sm.f.Al, tid);  __syncthreads();   // T1 = S*Al
    mmT32(sm.f.St, sm.f.Al, sm.f.T1, tid);  __syncthreads();   // St (symmetric)
    mm32 (sm.f.T2, sm.f.P2, sm.f.Al, tid);  __syncthreads();   // T2 = K*Al
    mmT32(sm.f.Kt, sm.f.Al, sm.f.T2, tid);  __syncthreads();   // Kt (symmetric)

    // ---- wait for this batch's 64 moment blocks ----
    if (tid == 0) {
        while (atomicAdd(&g_cnt[b], 0u) < (unsigned)BLK_PER_BATCH)
            __nanosleep(128);
    }
    __syncthreads();
    __threadfence();                        // acquire for g_W reads

    // ---- load moments, restore g_W for next replay ----
#pragma unroll
    for (int k = 0; k < 4; k++) {
        const int o = tid + TPB * k;
        const int r = o >> 5, c = o & 31;
        sm.f.Mx[r * PI + c] = __ldcg(&g_W[(b * 2 + 0) * NCH * NCH + o]);
        sm.f.My[r * PI + c] = __ldcg(&g_W[(b * 2 + 1) * NCH * NCH + o]);
        g_W[(b * 2 + 0) * NCH * NCH + o] = 0.0f;
        g_W[(b * 2 + 1) * NCH * NCH + o] = 0.0f;
    }
    __syncthreads();

    // ---- pass 1 (fused): P1 = My*Kt, P2 = My*St ----
#pragma unroll
    for (int k = 0; k < 4; k++) {
        const int o = tid + TPB * k;
        const int r = o >> 5, c = o & 31;
        float p1 = 0.0f, p2 = 0.0f;
#pragma unroll
        for (int i = 0; i < NCH; i++) {
            float my = sm.f.My[r * PI + i];             // broadcast
            p1 = fmaf(my, sm.f.Kt[i * PI + c], p1);     // coalesced
            p2 = fmaf(my, sm.f.St[i * PI + c], p2);
        }
        sm.f.T1[r * PI + c] = p1;
        sm.f.T2[r * PI + c] = p2;
    }
    __syncthreads();

    // ---- pass 2 (fused): q1 = St*Mx, q2 = Kt*Mx, dot against T1,T2 ----
    float acc = 0.0f;
#pragma unroll
    for (int k = 0; k < 4; k++) {
        const int o = tid + TPB * k;
        const int r = o >> 5, c = o & 31;
        float q1 = 0.0f, q2 = 0.0f;
#pragma unroll
        for (int i = 0; i < NCH; i++) {
            float st = sm.f.St[r * PI + i];             // broadcast (St sym)
            float kt = sm.f.Kt[r * PI + i];
            float mx = sm.f.Mx[i * PI + c];             // coalesced
            q1 = fmaf(st, mx, q1);
            q2 = fmaf(kt, mx, q2);
        }
        acc = fmaf(q1, sm.f.T1[r * PI + c], acc);       // <St Mx, My Kt>
        acc = fmaf(q2, sm.f.T2[r * PI + c], acc);       // <Kt Mx, My St>
    }

#pragma unroll
    for (int off = 16; off > 0; off >>= 1)
        acc += __shfl_xor_sync(0xffffffffu, acc, off);
    if ((tid & 31) == 0) sm.f.red[tid >> 5] = acc;
    __syncthreads();

    if (tid == 0) {
        float v = 0.0f;
#pragma unroll
        for (int w2 = 0; w2 < TPB / 32; w2++) v += sm.f.red[w2];
        out[b] = v;
        atomicExch(&g_cnt[b], 0u);          // restore counter for replay
    }
}

extern "C" void kernel_launch(void* const* d_in, const int* in_sizes, int n_in,
                              void* d_out, int out_size)
{
    const float* x  = (const float*)d_in[0];
    const float* y  = (const float*)d_in[1];
    const float* xs = (const float*)d_in[2];
    const float* ys = (const float*)d_in[3];
    float* out = (float*)d_out;
    (void)in_sizes; (void)n_in; (void)out_size;

    k_fused<<<GRID, TPB>>>(x, y, xs, ys, out);
}

// round 17
// speedup vs baseline: 1.8668x; 1.8668x over previous
#include <cuda_runtime.h>

// ---------------------------------------------------------------------------
// SinkhornDistance (degenerate loop):
//   out[b] = sum_{i,j} g(xs_i-ys_j, x_i-y_j), g(d1,d2)=c*exp(-10c), c=d1^2+d2^2
// Separable rank-2 => Chebyshev tensor algebra (n=32 first-kind nodes):
//   out[b] = <S, Wx K Wy^T> + <K, Wx S Wy^T>,
//   Wx[a,c] = sum_i L_a(xs_i) L_c(x_i),  Wy likewise for (ys, y).
// R17: R8 (best so far) with the GPU-scope __threadfence()s (each emits
// CCTL.IVALL => L1D flush per block on sm_103a) replaced by a single
// atom.add.acq_rel.gpu on the per-batch counter. Basis sum chain split x2.
// ---------------------------------------------------------------------------

#define NCH    32
#define NPTS   4096
#define NB     8
#define CHUNK  128
#define NCHUNK (NPTS / CHUNK)          // 32
#define BLK_PER_BATCH (2 * NCHUNK)     // 64
#define GRID   (NB * BLK_PER_BATCH)    // 512
#define TPB    256
#define NWARP  (TPB / 32)              // 8
#define PPW    (CHUNK / NWARP)         // 16 points per warp
#define PI     33                      // B pitch (floats), conflict-free

#define PACK2(out, lo, hi)  asm("mov.b64 %0, {%1, %2};" : "=l"(out) : "f"(lo), "f"(hi))
#define UNPACK2(lo, hi, in) asm("mov.b64 {%0, %1}, %2;" : "=f"(lo), "=f"(hi) : "l"(in))
#define FMA2(out, a, b, c)  asm("fma.rn.f32x2 %0, %1, %2, %3;" : "=l"(out) : "l"(a), "l"(b), "l"(c))

__device__ float g_W[NB * 2 * NCH * NCH];   // zero-init; re-zeroed by epilogue
__device__ unsigned int g_cnt[NB];          // per-batch arrivals; reset by owner

struct MomSh {
    unsigned long long A64[CHUNK * 16];     // [pt][swizzled a-pair], 16 KB
    float B[CHUNK * PI];                    // [pt][c]
    float node[NCH], wt[NCH];
};
struct FinSh {
    float Wx[NCH * PI], Wy[NCH * PI];
    float K [NCH * PI], S [NCH * PI];
    float P [NCH * PI], Q [NCH * PI];
    float red[NWARP];
};

__global__ void __launch_bounds__(TPB) k_fused(
    const float* __restrict__ x,  const float* __restrict__ y,
    const float* __restrict__ xs, const float* __restrict__ ys,
    float* __restrict__ out)
{
    __shared__ __align__(16) union { MomSh m; FinSh f; } sm;
    __shared__ int s_last;

    const int tid   = threadIdx.x;
    const int blk   = blockIdx.x;
    const int chunk = blk & (NCHUNK - 1);
    const int side  = (blk >> 5) & 1;
    const int batch = blk >> 6;

    // ---------------- phase 1: moment contribution ----------------
    if (tid < NCH) {
        float u = (2.0f * tid + 1.0f) / (2.0f * NCH);
        sm.m.node[tid] = cospif(u);
        float s = sinpif(u);
        sm.m.wt[tid] = (tid & 1) ? -s : s;
    }
    __syncthreads();

    const float* A  = side ? ys : xs;       // support coord -> index a
    const float* Bv = side ? y  : x;        // value coord   -> index c
    const int base  = batch * NPTS + chunk * CHUNK;

    // Barycentric Lagrange basis: 256 tasks = 1 per thread
    {
        const int pt    = tid & (CHUNK - 1);
        const int which = tid >> 7;
        float v  = which ? Bv[base + pt] : A[base + pt];
        float xi = 2.0f * v - 1.0f;
        float tv[NCH];
        float s0 = 0.0f, s1 = 0.0f;         // split dependence chain
#pragma unroll
        for (int a = 0; a < NCH; a += 2) {
            float d0 = xi - sm.m.node[a];
            float d1 = xi - sm.m.node[a + 1];
            d0 = copysignf(fmaxf(fabsf(d0), 1e-12f), d0);
            d1 = copysignf(fmaxf(fabsf(d1), 1e-12f), d1);
            float q0 = __fdividef(sm.m.wt[a],     d0);
            float q1 = __fdividef(sm.m.wt[a + 1], d1);
            tv[a]     = q0;
            tv[a + 1] = q1;
            s0 += q0;
            s1 += q1;
        }
        float inv = __fdividef(1.0f, s0 + s1);
        if (which) {
#pragma unroll
            for (int a = 0; a < NCH; a++) sm.m.B[pt * PI + a] = tv[a] * inv;
        } else {
            const int sw = pt & 15;
#pragma unroll
            for (int a2 = 0; a2 < 16; a2++) {
                unsigned long long pr;
                PACK2(pr, tv[2 * a2] * inv, tv[2 * a2 + 1] * inv);
                sm.m.A64[pt * 16 + (a2 ^ sw)] = pr;   // 2-way conflict store
            }
        }
    }
    __syncthreads();

    // Outer-product: warp owns 16 points x all 32 c-columns; a-rows packed x2
    {
        const int w    = tid >> 5;
        const int lane = tid & 31;
        const int p0   = w * PPW;               // multiple of 16 -> sw == i

        unsigned long long acc[NCH / 2];
#pragma unroll
        for (int a2 = 0; a2 < NCH / 2; a2++) acc[a2] = 0ull;

#pragma unroll 4
        for (int i = 0; i < PPW; i++) {
            const int pt = p0 + i;
            float bv = sm.m.B[pt * PI + lane];              // coalesced
            unsigned long long bv2;
            PACK2(bv2, bv, bv);
            const unsigned long long* arow = sm.m.A64 + pt * 16;
#pragma unroll
            for (int a2 = 0; a2 < NCH / 2; a2++)
                FMA2(acc[a2], arow[a2 ^ i], bv2, acc[a2]);  // LDS.64 broadcast
        }

        __syncthreads();
        float* red = reinterpret_cast<float*>(sm.m.A64);    // 8x1024 floats
#pragma unroll
        for (int a2 = 0; a2 < NCH / 2; a2++) {
            float lo, hi;
            UNPACK2(lo, hi, acc[a2]);
            red[w * 1024 + (2 * a2)     * NCH + lane] = lo; // conflict-free
            red[w * 1024 + (2 * a2 + 1) * NCH + lane] = hi;
        }
        __syncthreads();

        float* Wp = g_W + (batch * 2 + side) * NCH * NCH;
#pragma unroll
        for (int k = 0; k < 4; k++) {
            int o = tid + 256 * k;              // coalesced, conflict-free
            float v = 0.0f;
#pragma unroll
            for (int w2 = 0; w2 < NWARP; w2++) v += red[w2 * 1024 + o];
            atomicAdd(&Wp[o], v);               // RED, no return
        }
    }

    // ---------------- per-batch last-block election ----------------
    // acq_rel atomic replaces __threadfence (which emits CCTL.IVALL = full
    // L1D flush per block on sm_103a). Release orders this block's REDs
    // (bar.sync drains them CTA-wide first); acquire covers the epilogue's
    // g_W reads, propagated block-wide by the following __syncthreads.
    __syncthreads();
    if (tid == 0) {
        unsigned prev;
        asm volatile("atom.add.acq_rel.gpu.global.u32 %0, [%1], %2;"
                     : "=r"(prev) : "l"(&g_cnt[batch]), "r"(1u) : "memory");
        s_last = (prev == BLK_PER_BATCH - 1);
    }
    __syncthreads();
    if (!s_last) return;

    const int b = batch;

    // ---------------- epilogue: contraction for batch b ----------------
    for (int k = tid; k < NCH * NCH; k += TPB) {
        const int a = k >> 5, d = k & 31;
        float wx = __ldcg(&g_W[(b * 2 + 0) * NCH * NCH + k]);
        float wy = __ldcg(&g_W[(b * 2 + 1) * NCH * NCH + k]);
        sm.f.Wx[a * PI + d] = wx;
        sm.f.Wy[a * PI + d] = wy;
        g_W[(b * 2 + 0) * NCH * NCH + k] = 0.0f;   // restore for next replay
        g_W[(b * 2 + 1) * NCH * NCH + k] = 0.0f;
        float pa = cospif((2.0f * a + 1.0f) / (2.0f * NCH));
        float pc = cospif((2.0f * d + 1.0f) / (2.0f * NCH));
        float dd = 0.5f * (pa - pc);
        float c2 = dd * dd;
        float e  = expf(-10.0f * c2);
        sm.f.K[a * PI + d] = e;
        sm.f.S[a * PI + d] = c2 * e;
    }
    __syncthreads();

    // P = Wx*K, Q = Wx*S
    for (int e = tid; e < NCH * NCH; e += TPB) {
        const int a = e >> 5, d = e & 31;
        float p = 0.0f, q = 0.0f;
#pragma unroll
        for (int bb = 0; bb < NCH; bb++) {
            float wv = sm.f.Wx[a * PI + bb];
            p = fmaf(wv, sm.f.K[bb * PI + d], p);
            q = fmaf(wv, sm.f.S[bb * PI + d], q);
        }
        sm.f.P[a * PI + d] = p;
        sm.f.Q[a * PI + d] = q;
    }
    __syncthreads();

    // sum of S.*(P*Wy^T) + K.*(Q*Wy^T)
    float acc = 0.0f;
    for (int e = tid; e < NCH * NCH; e += TPB) {
        const int a = e >> 5, c = e & 31;
        float m = 0.0f, n = 0.0f;
#pragma unroll
        for (int dd = 0; dd < NCH; dd++) {
            float wy = sm.f.Wy[c * PI + dd];
            m = fmaf(sm.f.P[a * PI + dd], wy, m);
            n = fmaf(sm.f.Q[a * PI + dd], wy, n);
        }
        acc += sm.f.S[a * PI + c] * m + sm.f.K[a * PI + c] * n;
    }
#pragma unroll
    for (int off = 16; off > 0; off >>= 1)
        acc += __shfl_xor_sync(0xffffffffu, acc, off);
    if ((tid & 31) == 0) sm.f.red[tid >> 5] = acc;
    __syncthreads();

    if (tid == 0) {
        float v = 0.0f;
#pragma unroll
        for (int w2 = 0; w2 < NWARP; w2++) v += sm.f.red[w2];
        out[b] = v;
        // relaxed reset is fine: next replay's uses are ordered by the
        // graph-level kernel boundary.
        atomicExch(&g_cnt[b], 0u);
    }
}

extern "C" void kernel_launch(void* const* d_in, const int* in_sizes, int n_in,
                              void* d_out, int out_size)
{
    const float* x  = (const float*)d_in[0];
    const float* y  = (const float*)d_in[1];
    const float* xs = (const float*)d_in[2];
    const float* ys = (const float*)d_in[3];
    float* out = (float*)d_out;
    (void)in_sizes; (void)n_in; (void)out_size;

    k_fused<<<GRID, TPB>>>(x, y, xs, ys, out);
}